// round 1
// baseline (speedup 1.0000x reference)
#include <cuda_runtime.h>
#include <math.h>

#define NNODES 100000
#define NEDGES 1600000
#define NGRAPH 64
#define NEGS   0.2f

// ---------------- scratch (static device globals; no allocation) ----------------
__device__ float g_xl1[NNODES * 128];
__device__ float g_xr1[NNODES * 128];
__device__ float g_h1 [NNODES * 128];
__device__ float g_xl2[NNODES * 64];
__device__ float g_xr2[NNODES * 64];
__device__ int   g_deg[NNODES];
__device__ int   g_rowptr[NNODES + 1];
__device__ int   g_cursor[NNODES];
__device__ int   g_srcs[NEDGES];
__device__ float g_gsum[NGRAPH * 64];
__device__ int   g_gcnt[NGRAPH];
__device__ int   g_bsum[128];

// ---------------- init / CSR build ----------------
__global__ void k_zero() {
    int i = blockIdx.x * blockDim.x + threadIdx.x;
    if (i < NNODES) g_deg[i] = 0;
    if (i < NGRAPH * 64) g_gsum[i] = 0.f;
    if (i < NGRAPH) g_gcnt[i] = 0;
}

__global__ void k_hist(const int* __restrict__ ei) {
    int e = blockIdx.x * blockDim.x + threadIdx.x;
    if (e < NEDGES) atomicAdd(&g_deg[ei[NEDGES + e]], 1);
}

__global__ void k_scan1() {
    __shared__ int sh[1024];
    int t = threadIdx.x;
    int i = blockIdx.x * 1024 + t;
    int v = (i < NNODES) ? g_deg[i] : 0;
    sh[t] = v;
    __syncthreads();
    for (int off = 1; off < 1024; off <<= 1) {
        int add = (t >= off) ? sh[t - off] : 0;
        __syncthreads();
        sh[t] += add;
        __syncthreads();
    }
    if (i < NNODES) g_rowptr[i] = sh[t] - v;   // exclusive
    if (t == 1023) g_bsum[blockIdx.x] = sh[1023];
}

__global__ void k_scan2(int nb) {
    if (threadIdx.x == 0 && blockIdx.x == 0) {
        int run = 0;
        for (int b = 0; b < nb; b++) { int v = g_bsum[b]; g_bsum[b] = run; run += v; }
    }
}

__global__ void k_scan3() {
    int t = threadIdx.x;
    int i = blockIdx.x * 1024 + t;
    if (i < NNODES) {
        int r = g_rowptr[i] + g_bsum[blockIdx.x];
        g_rowptr[i] = r;
        g_cursor[i] = r;
    }
    if (i == 0) g_rowptr[NNODES] = NEDGES;
}

__global__ void k_scatter(const int* __restrict__ ei) {
    int e = blockIdx.x * blockDim.x + threadIdx.x;
    if (e < NEDGES) {
        int d = ei[NEDGES + e];
        int pos = atomicAdd(&g_cursor[d], 1);
        g_srcs[pos] = ei[e];
    }
}

// ---------------- SGEMM: C[n,M] = A[n,K] @ W[K,M] + bias ----------------
// BM=128, BN=64, BK=16, 256 threads, 8x4 thread tile.
__global__ __launch_bounds__(256) void k_sgemm(
    const float* __restrict__ A, const float* __restrict__ W,
    const float* __restrict__ bias, float* __restrict__ C,
    int n, int K, int M)
{
    __shared__ float As[128][17];   // padded: conflict-free stores & reads
    __shared__ float Ws[16][64];    // float4-read aligned

    int tid  = threadIdx.x;
    int row0 = blockIdx.x * 128;
    int col0 = blockIdx.y * 64;
    int tx = tid & 15;      // 16 col-groups * 4 cols
    int ty = tid >> 4;      // 16 row-groups * 8 rows

    float acc[8][4];
#pragma unroll
    for (int i = 0; i < 8; i++)
#pragma unroll
        for (int j = 0; j < 4; j++) acc[i][j] = 0.f;

    for (int kb = 0; kb < K; kb += 16) {
#pragma unroll
        for (int i = tid; i < 128 * 16; i += 256) {
            int m = i >> 4, k = i & 15;
            int r = row0 + m;
            As[m][k] = (r < n) ? A[r * K + kb + k] : 0.f;
        }
#pragma unroll
        for (int i = tid; i < 16 * 64; i += 256) {
            int k = i >> 6, c = i & 63;
            Ws[k][c] = W[(kb + k) * M + col0 + c];
        }
        __syncthreads();
#pragma unroll
        for (int k = 0; k < 16; k++) {
            float a[8];
#pragma unroll
            for (int i = 0; i < 8; i++) a[i] = As[ty * 8 + i][k];
            float4 bv = *reinterpret_cast<const float4*>(&Ws[k][tx * 4]);
            float b[4] = {bv.x, bv.y, bv.z, bv.w};
#pragma unroll
            for (int i = 0; i < 8; i++)
#pragma unroll
                for (int j = 0; j < 4; j++) acc[i][j] += a[i] * b[j];
        }
        __syncthreads();
    }
#pragma unroll
    for (int i = 0; i < 8; i++) {
        int r = row0 + ty * 8 + i;
        if (r < n) {
#pragma unroll
            for (int j = 0; j < 4; j++) {
                int c = col0 + tx * 4 + j;
                C[r * M + c] = acc[i][j] + bias[c];
            }
        }
    }
}

// ---------------- layer 1: warp-per-dst online segment softmax + LN + ELU ----------------
__global__ __launch_bounds__(256) void k_agg1(
    const float* __restrict__ att, const float* __restrict__ bias1,
    const float* __restrict__ g1, const float* __restrict__ be1)
{
    int node = (blockIdx.x * blockDim.x + threadIdx.x) >> 5;
    if (node >= NNODES) return;
    int lane = threadIdx.x & 31;

    const float* xr = g_xr1 + node * 128;
    float xr0 = xr[lane], xr1 = xr[lane + 32], xr2 = xr[lane + 64], xr3 = xr[lane + 96];
    float a0 = att[lane], a1 = att[lane + 32], a2 = att[lane + 64], a3 = att[lane + 96];

    float m0 = -1e30f, m1 = -1e30f, d0 = 0.f, d1 = 0.f;
    float c0 = 0.f, c1 = 0.f, c2 = 0.f, c3 = 0.f;

    int beg = g_rowptr[node], end = g_rowptr[node + 1];
    for (int i = beg; i < end; i++) {
        int s = g_srcs[i];
        const float* xl = g_xl1 + s * 128;
        float v0 = xl[lane], v1 = xl[lane + 32], v2 = xl[lane + 64], v3 = xl[lane + 96];
        float e0 = v0 + xr0; e0 = (e0 > 0.f) ? e0 : NEGS * e0;
        float e1 = v1 + xr1; e1 = (e1 > 0.f) ? e1 : NEGS * e1;
        float e2 = v2 + xr2; e2 = (e2 > 0.f) ? e2 : NEGS * e2;
        float e3 = v3 + xr3; e3 = (e3 > 0.f) ? e3 : NEGS * e3;
        float p0 = a0 * e0 + a1 * e1;   // head 0 partial
        float p1 = a2 * e2 + a3 * e3;   // head 1 partial
#pragma unroll
        for (int off = 16; off; off >>= 1) {
            p0 += __shfl_xor_sync(0xffffffffu, p0, off);
            p1 += __shfl_xor_sync(0xffffffffu, p1, off);
        }
        float nm0 = fmaxf(m0, p0), nm1 = fmaxf(m1, p1);
        float s0 = __expf(m0 - nm0), s1 = __expf(m1 - nm1);
        float w0 = __expf(p0 - nm0), w1 = __expf(p1 - nm1);
        d0 = d0 * s0 + w0;          d1 = d1 * s1 + w1;
        c0 = c0 * s0 + w0 * v0;     c1 = c1 * s0 + w0 * v1;
        c2 = c2 * s1 + w1 * v2;     c3 = c3 * s1 + w1 * v3;
        m0 = nm0; m1 = nm1;
    }
    float i0 = 1.f / (d0 + 1e-16f), i1 = 1.f / (d1 + 1e-16f);
    float o0 = c0 * i0 + bias1[lane];
    float o1 = c1 * i0 + bias1[lane + 32];
    float o2 = c2 * i1 + bias1[lane + 64];
    float o3 = c3 * i1 + bias1[lane + 96];

    // fused LayerNorm over 128 feats
    float sum = o0 + o1 + o2 + o3;
    float sq  = o0 * o0 + o1 * o1 + o2 * o2 + o3 * o3;
#pragma unroll
    for (int off = 16; off; off >>= 1) {
        sum += __shfl_xor_sync(0xffffffffu, sum, off);
        sq  += __shfl_xor_sync(0xffffffffu, sq,  off);
    }
    float mu = sum * (1.f / 128.f);
    float var = sq * (1.f / 128.f) - mu * mu;
    float rs = rsqrtf(var + 1e-5f);

    float* ho = g_h1 + node * 128;
    float t;
    t = (o0 - mu) * rs * g1[lane]      + be1[lane];      ho[lane]      = (t > 0.f) ? t : expm1f(t);
    t = (o1 - mu) * rs * g1[lane + 32] + be1[lane + 32]; ho[lane + 32] = (t > 0.f) ? t : expm1f(t);
    t = (o2 - mu) * rs * g1[lane + 64] + be1[lane + 64]; ho[lane + 64] = (t > 0.f) ? t : expm1f(t);
    t = (o3 - mu) * rs * g1[lane + 96] + be1[lane + 96]; ho[lane + 96] = (t > 0.f) ? t : expm1f(t);
}

// ---------------- layer 2: warp-per-dst online segment softmax ----------------
__global__ __launch_bounds__(256) void k_agg2(
    const float* __restrict__ att2, const float* __restrict__ bias2,
    float* __restrict__ out)
{
    int node = (blockIdx.x * blockDim.x + threadIdx.x) >> 5;
    if (node >= NNODES) return;
    int lane = threadIdx.x & 31;

    float xr0 = g_xr2[node * 64 + lane];
    float xr1 = g_xr2[node * 64 + lane + 32];
    float a0 = att2[lane], a1 = att2[lane + 32];

    float m = -1e30f, d = 0.f, c0 = 0.f, c1 = 0.f;
    int beg = g_rowptr[node], end = g_rowptr[node + 1];
    for (int i = beg; i < end; i++) {
        int s = g_srcs[i];
        float v0 = g_xl2[s * 64 + lane];
        float v1 = g_xl2[s * 64 + lane + 32];
        float e0 = v0 + xr0; e0 = (e0 > 0.f) ? e0 : NEGS * e0;
        float e1 = v1 + xr1; e1 = (e1 > 0.f) ? e1 : NEGS * e1;
        float p = a0 * e0 + a1 * e1;
#pragma unroll
        for (int off = 16; off; off >>= 1) p += __shfl_xor_sync(0xffffffffu, p, off);
        float nm = fmaxf(m, p);
        float sc = __expf(m - nm);
        float w  = __expf(p - nm);
        d  = d  * sc + w;
        c0 = c0 * sc + w * v0;
        c1 = c1 * sc + w * v1;
        m = nm;
    }
    float inv = 1.f / (d + 1e-16f);
    out[node * 64 + lane]      = c0 * inv + bias2[lane];
    out[node * 64 + lane + 32] = c1 * inv + bias2[lane + 32];
}

// ---------------- global mean pool ----------------
__global__ __launch_bounds__(256) void k_pool(const int* __restrict__ batch,
                                              const float* __restrict__ emb)
{
    int node = (blockIdx.x * blockDim.x + threadIdx.x) >> 5;
    if (node >= NNODES) return;
    int lane = threadIdx.x & 31;
    int g = batch[node];
    atomicAdd(&g_gsum[g * 64 + lane],      emb[node * 64 + lane]);
    atomicAdd(&g_gsum[g * 64 + lane + 32], emb[node * 64 + lane + 32]);
    if (lane == 0) atomicAdd(&g_gcnt[g], 1);
}

__global__ void k_final(float* __restrict__ out) {
    int i = blockIdx.x * blockDim.x + threadIdx.x;
    if (i < NGRAPH * 64) {
        int g = i >> 6;
        float cnt = (float)g_gcnt[g];
        out[NNODES * 64 + i] = g_gsum[i] / fmaxf(cnt, 1.f);
    }
}

// ---------------- launch ----------------
extern "C" void kernel_launch(void* const* d_in, const int* in_sizes, int n_in,
                              void* d_out, int out_size)
{
    const float* x     = (const float*)d_in[0];
    const int*   ei    = (const int*)  d_in[1];
    const int*   batch = (const int*)  d_in[2];
    const float* W1l   = (const float*)d_in[3];
    const float* b1l   = (const float*)d_in[4];
    const float* W1r   = (const float*)d_in[5];
    const float* b1r   = (const float*)d_in[6];
    const float* att1  = (const float*)d_in[7];
    const float* bias1 = (const float*)d_in[8];
    const float* g1    = (const float*)d_in[9];
    const float* be1   = (const float*)d_in[10];
    const float* W2l   = (const float*)d_in[11];
    const float* b2l   = (const float*)d_in[12];
    const float* W2r   = (const float*)d_in[13];
    const float* b2r   = (const float*)d_in[14];
    const float* att2  = (const float*)d_in[15];
    const float* bias2 = (const float*)d_in[16];
    float* out = (float*)d_out;

    float *xl1p, *xr1p, *h1p, *xl2p, *xr2p;
    cudaGetSymbolAddress((void**)&xl1p, g_xl1);
    cudaGetSymbolAddress((void**)&xr1p, g_xr1);
    cudaGetSymbolAddress((void**)&h1p,  g_h1);
    cudaGetSymbolAddress((void**)&xl2p, g_xl2);
    cudaGetSymbolAddress((void**)&xr2p, g_xr2);

    // CSR build (shared by both layers)
    k_zero<<<(NNODES + 255) / 256, 256>>>();
    k_hist<<<(NEDGES + 255) / 256, 256>>>(ei);
    int nb = (NNODES + 1023) / 1024;
    k_scan1<<<nb, 1024>>>();
    k_scan2<<<1, 1>>>(nb);
    k_scan3<<<nb, 1024>>>();
    k_scatter<<<(NEDGES + 255) / 256, 256>>>(ei);

    // layer 1
    dim3 gg1((NNODES + 127) / 128, 2);
    k_sgemm<<<gg1, 256>>>(x, W1l, b1l, xl1p, NNODES, 128, 128);
    k_sgemm<<<gg1, 256>>>(x, W1r, b1r, xr1p, NNODES, 128, 128);
    int aggBlocks = (NNODES + 7) / 8;   // 8 warps per 256-thread block
    k_agg1<<<aggBlocks, 256>>>(att1, bias1, g1, be1);

    // layer 2
    dim3 gg2((NNODES + 127) / 128, 1);
    k_sgemm<<<gg2, 256>>>(h1p, W2l, b2l, xl2p, NNODES, 128, 64);
    k_sgemm<<<gg2, 256>>>(h1p, W2r, b2r, xr2p, NNODES, 128, 64);
    k_agg2<<<aggBlocks, 256>>>(att2, bias2, out);

    // pooling (only if the output buffer carries graph_emb too)
    if (out_size >= NNODES * 64 + NGRAPH * 64) {
        k_pool<<<aggBlocks, 256>>>(batch, out);
        k_final<<<(NGRAPH * 64 + 255) / 256, 256>>>(out);
    }
}

// round 3
// speedup vs baseline: 1.3108x; 1.3108x over previous
#include <cuda_runtime.h>
#include <cuda_bf16.h>
#include <math.h>
#include <stdint.h>

#define NNODES 100000
#define NEDGES 1600000
#define NGRAPH 64
#define NEGS   0.2f

// ---------------- scratch (static device globals; no allocation) ----------------
__device__ float g_xlr1[(size_t)NNODES * 256];   // layer1 GEMM out: [xl1 | xr1]
__device__ float g_h1 [(size_t)NNODES * 128];    // post LN+ELU
__device__ float g_xlr2[(size_t)NNODES * 128];   // layer2 GEMM out: [xl2 | xr2]
__device__ __align__(16) __nv_bfloat16 g_B1e[256 * 256];  // [n][kext]: [Wh | Wl]
__device__ __align__(16) __nv_bfloat16 g_B2e[128 * 256];
__device__ float g_bias1[256];
__device__ float g_bias2[128];
__device__ int   g_deg[NNODES];
__device__ int   g_rowptr[NNODES + 1];
__device__ int   g_cursor[NNODES];
__device__ int   g_srcs[NEDGES];
__device__ float g_gsum[NGRAPH * 64];
__device__ int   g_gcnt[NGRAPH];
__device__ int   g_bsum[128];

// ---------------- weight pre-split (fp32 -> bf16 hi/lo, [N][Kext] K-major) ----------------
__global__ void k_prep(const float* __restrict__ W1l, const float* __restrict__ W1r,
                       const float* __restrict__ b1l, const float* __restrict__ b1r,
                       const float* __restrict__ W2l, const float* __restrict__ W2r,
                       const float* __restrict__ b2l, const float* __restrict__ b2r)
{
    int i = blockIdx.x * blockDim.x + threadIdx.x;   // up to 65536
    if (i < 256 * 256) {
        int n = i >> 8, ke = i & 255;
        int k = ke & 127;
        float w = (n < 128) ? W1l[k * 128 + n] : W1r[k * 128 + (n - 128)];
        __nv_bfloat16 h = __float2bfloat16(w);
        g_B1e[i] = (ke < 128) ? h : __float2bfloat16(w - __bfloat162float(h));
    }
    if (i < 128 * 256) {
        int n = i >> 8, ke = i & 255;
        int k = ke & 127;
        float w = (n < 64) ? W2l[k * 64 + n] : W2r[k * 64 + (n - 64)];
        __nv_bfloat16 h = __float2bfloat16(w);
        g_B2e[i] = (ke < 128) ? h : __float2bfloat16(w - __bfloat162float(h));
    }
    if (i < 256) g_bias1[i] = (i < 128) ? b1l[i] : b1r[i - 128];
    if (i < 128) g_bias2[i] = (i < 64) ? b2l[i] : b2r[i - 64];
}

// ---------------- init / CSR build ----------------
__global__ void k_zero() {
    int i = blockIdx.x * blockDim.x + threadIdx.x;
    if (i < NNODES) g_deg[i] = 0;
    if (i < NGRAPH * 64) g_gsum[i] = 0.f;
    if (i < NGRAPH) g_gcnt[i] = 0;
}

__global__ void k_hist(const int* __restrict__ ei) {
    int e = blockIdx.x * blockDim.x + threadIdx.x;
    if (e < NEDGES) atomicAdd(&g_deg[ei[NEDGES + e]], 1);
}

__global__ void k_scan1() {
    __shared__ int sh[1024];
    int t = threadIdx.x;
    int i = blockIdx.x * 1024 + t;
    int v = (i < NNODES) ? g_deg[i] : 0;
    sh[t] = v;
    __syncthreads();
    for (int off = 1; off < 1024; off <<= 1) {
        int add = (t >= off) ? sh[t - off] : 0;
        __syncthreads();
        sh[t] += add;
        __syncthreads();
    }
    if (i < NNODES) g_rowptr[i] = sh[t] - v;   // exclusive
    if (t == 1023) g_bsum[blockIdx.x] = sh[1023];
}

__global__ void k_scan2(int nb) {   // parallel 128-wide block scan
    __shared__ int sh[128];
    int t = threadIdx.x;
    int v = (t < nb) ? g_bsum[t] : 0;
    sh[t] = v;
    __syncthreads();
    for (int off = 1; off < 128; off <<= 1) {
        int add = (t >= off) ? sh[t - off] : 0;
        __syncthreads();
        sh[t] += add;
        __syncthreads();
    }
    if (t < nb) g_bsum[t] = sh[t] - v;          // exclusive
}

__global__ void k_scan3() {
    int t = threadIdx.x;
    int i = blockIdx.x * 1024 + t;
    if (i < NNODES) {
        int r = g_rowptr[i] + g_bsum[blockIdx.x];
        g_rowptr[i] = r;
        g_cursor[i] = r;
    }
    if (i == 0) g_rowptr[NNODES] = NEDGES;
}

__global__ void k_scatter(const int* __restrict__ ei) {
    int e = blockIdx.x * blockDim.x + threadIdx.x;
    if (e < NEDGES) {
        int d = ei[NEDGES + e];
        int pos = atomicAdd(&g_cursor[d], 1);
        g_srcs[pos] = ei[e];
    }
}

// ---------------- HMMA bf16 split-GEMM: C[n,Ntot] = A[n,128] @ W + bias ----------------
// mma.sync.m16n8k16 (baseline PTX, works on plain sm_103 target).
// Block tile: M=128 x N=128, whole K resident. 3-term split = 6 sections of K=64.
// SMEM: Ah[128][128]bf16 (+pad), Al[128][128]bf16, Bext[128][256]bf16.

#define ASTR 272          // 128*2 + 16 pad  (17 x 16B -> conflict-free ldmatrix)
#define BSTR 528          // 256*2 + 16 pad  (33 x 16B)
#define SM_AH 0
#define SM_AL (128 * ASTR)
#define SM_B  (2 * 128 * ASTR)
#define SM_TOT (SM_B + 128 * BSTR)   // 137216 bytes

__device__ __forceinline__ uint32_t s2u(const void* p) {
    uint32_t a;
    asm("{ .reg .u64 t; cvta.to.shared.u64 t, %1; cvt.u32.u64 %0, t; }" : "=r"(a) : "l"(p));
    return a;
}
__device__ __forceinline__ uint32_t pk(__nv_bfloat16 a, __nv_bfloat16 b) {
    return (uint32_t)__bfloat16_as_ushort(a) | ((uint32_t)__bfloat16_as_ushort(b) << 16);
}

#define LDSM4(d0, d1, d2, d3, addr) \
    asm volatile("ldmatrix.sync.aligned.m8n8.x4.shared.b16 {%0,%1,%2,%3}, [%4];" \
                 : "=r"(d0), "=r"(d1), "=r"(d2), "=r"(d3) : "r"(addr))

#define MMA16816(c, a0, a1, a2, a3, b0, b1) \
    asm volatile("mma.sync.aligned.m16n8k16.row.col.f32.bf16.bf16.f32 " \
                 "{%0,%1,%2,%3}, {%4,%5,%6,%7}, {%8,%9}, {%0,%1,%2,%3};" \
                 : "+f"((c)[0]), "+f"((c)[1]), "+f"((c)[2]), "+f"((c)[3]) \
                 : "r"(a0), "r"(a1), "r"(a2), "r"(a3), "r"(b0), "r"(b1))

__global__ __launch_bounds__(256, 1)
void k_hmma(const float* __restrict__ A, const __nv_bfloat16* __restrict__ Bext,
            const float* __restrict__ bias, float* __restrict__ C,
            int nrows, int Ntot)
{
    extern __shared__ char smem[];
    const uint32_t sb = s2u(smem);
    const int tid = threadIdx.x;
    const int lane = tid & 31, wid = tid >> 5;
    const int wm = wid >> 2, wn = wid & 3;          // warp tile: M64 x N32 in 2x4 grid
    const int row0 = blockIdx.x * 128;
    const int ncol0 = blockIdx.y * 128;

    // ---- load & split A [128 x 128] fp32 -> Ah/Al bf16 smem ----
#pragma unroll
    for (int i = 0; i < 16; i++) {
        int idx = tid + (i << 8);
        int r = idx >> 5, c4 = idx & 31;            // c4*4 = fp32 col
        float4 v = make_float4(0.f, 0.f, 0.f, 0.f);
        if (row0 + r < nrows)
            v = *(const float4*)(A + (size_t)(row0 + r) * 128 + c4 * 4);
        __nv_bfloat16 hx = __float2bfloat16(v.x), hy = __float2bfloat16(v.y),
                      hz = __float2bfloat16(v.z), hw = __float2bfloat16(v.w);
        uint32_t off = (uint32_t)(r * ASTR + c4 * 8);
        *(uint2*)(smem + SM_AH + off) = make_uint2(pk(hx, hy), pk(hz, hw));
        *(uint2*)(smem + SM_AL + off) = make_uint2(
            pk(__float2bfloat16(v.x - __bfloat162float(hx)),
               __float2bfloat16(v.y - __bfloat162float(hy))),
            pk(__float2bfloat16(v.z - __bfloat162float(hz)),
               __float2bfloat16(v.w - __bfloat162float(hw))));
    }
    // ---- load Bext tile [128 n x 256 kext] bf16 ----
#pragma unroll
    for (int i = 0; i < 16; i++) {
        int idx = tid + (i << 8);
        int n = idx >> 5, q = idx & 31;             // q = 16B unit
        *(uint4*)(smem + SM_B + n * BSTR + q * 16) =
            *(const uint4*)(Bext + (size_t)(ncol0 + n) * 256 + q * 8);
    }
    __syncthreads();

    float acc[4][4][4];
#pragma unroll
    for (int mf = 0; mf < 4; mf++)
#pragma unroll
        for (int nf = 0; nf < 4; nf++)
#pragma unroll
            for (int j = 0; j < 4; j++) acc[mf][nf][j] = 0.f;

    // per-lane ldmatrix address components
    const int aRow = lane & 15;                     // row within 16-row frag
    const int aColH = (lane >> 4) * 8;              // 0 / 8 (k half)
    const int bRow = (lane & 7) + ((lane & 16) ? 8 : 0);   // n within 16
    const int bColH = (lane & 8) ? 8 : 0;                  // k half

    // 6 K-sections: {Ah,Bh0},{Ah,Bh1},{Ah,Bl0},{Ah,Bl1},{Al,Bh0},{Al,Bh1}
#pragma unroll
    for (int sec = 0; sec < 6; sec++) {
        const uint32_t aBase = sb + ((sec < 4) ? SM_AH : SM_AL);
        const int acol = (sec & 1) * 64;
        const int bk = (sec < 2) ? sec * 64 : (sec < 4) ? 128 + (sec - 2) * 64 : (sec - 4) * 64;
#pragma unroll
        for (int kk = 0; kk < 4; kk++) {
            const int k16 = kk * 16;
            uint32_t br[2][4];
#pragma unroll
            for (int g = 0; g < 2; g++) {
                uint32_t ba = sb + SM_B + (uint32_t)((wn * 32 + g * 16 + bRow) * BSTR
                                                    + (bk + k16 + bColH) * 2);
                LDSM4(br[g][0], br[g][1], br[g][2], br[g][3], ba);
            }
#pragma unroll
            for (int mf = 0; mf < 4; mf++) {
                uint32_t a0, a1, a2, a3;
                uint32_t aa = aBase + (uint32_t)((wm * 64 + mf * 16 + aRow) * ASTR
                                                 + (acol + k16 + aColH) * 2);
                LDSM4(a0, a1, a2, a3, aa);
                MMA16816(acc[mf][0], a0, a1, a2, a3, br[0][0], br[0][1]);
                MMA16816(acc[mf][1], a0, a1, a2, a3, br[0][2], br[0][3]);
                MMA16816(acc[mf][2], a0, a1, a2, a3, br[1][0], br[1][1]);
                MMA16816(acc[mf][3], a0, a1, a2, a3, br[1][2], br[1][3]);
            }
        }
    }

    // ---- epilogue: bias + store ----
    const int rq = lane >> 2, cq = (lane & 3) * 2;
#pragma unroll
    for (int mf = 0; mf < 4; mf++) {
        int r = row0 + wm * 64 + mf * 16 + rq;
#pragma unroll
        for (int nf = 0; nf < 4; nf++) {
            int col = ncol0 + wn * 32 + nf * 8 + cq;
            float b0 = bias[col], b1 = bias[col + 1];
            if (r < nrows)
                *(float2*)(C + (size_t)r * Ntot + col) =
                    make_float2(acc[mf][nf][0] + b0, acc[mf][nf][1] + b1);
            if (r + 8 < nrows)
                *(float2*)(C + (size_t)(r + 8) * Ntot + col) =
                    make_float2(acc[mf][nf][2] + b0, acc[mf][nf][3] + b1);
        }
    }
}

// ---------------- layer 1: warp-per-dst online segment softmax + LN + ELU ----------------
__global__ __launch_bounds__(256) void k_agg1(
    const float* __restrict__ att, const float* __restrict__ bias1,
    const float* __restrict__ g1, const float* __restrict__ be1)
{
    int node = (blockIdx.x * blockDim.x + threadIdx.x) >> 5;
    if (node >= NNODES) return;
    int lane = threadIdx.x & 31;

    const float* xr = g_xlr1 + (size_t)node * 256 + 128;
    float xr0 = xr[lane], xr1 = xr[lane + 32], xr2 = xr[lane + 64], xr3 = xr[lane + 96];
    float a0 = att[lane], a1 = att[lane + 32], a2 = att[lane + 64], a3 = att[lane + 96];

    float m0 = -1e30f, m1 = -1e30f, d0 = 0.f, d1 = 0.f;
    float c0 = 0.f, c1 = 0.f, c2 = 0.f, c3 = 0.f;

    int beg = g_rowptr[node], end = g_rowptr[node + 1];
    for (int i = beg; i < end; i++) {
        int s = g_srcs[i];
        const float* xl = g_xlr1 + (size_t)s * 256;
        float v0 = xl[lane], v1 = xl[lane + 32], v2 = xl[lane + 64], v3 = xl[lane + 96];
        float e0 = v0 + xr0; e0 = (e0 > 0.f) ? e0 : NEGS * e0;
        float e1 = v1 + xr1; e1 = (e1 > 0.f) ? e1 : NEGS * e1;
        float e2 = v2 + xr2; e2 = (e2 > 0.f) ? e2 : NEGS * e2;
        float e3 = v3 + xr3; e3 = (e3 > 0.f) ? e3 : NEGS * e3;
        float p0 = a0 * e0 + a1 * e1;   // head 0 partial
        float p1 = a2 * e2 + a3 * e3;   // head 1 partial
#pragma unroll
        for (int off = 16; off; off >>= 1) {
            p0 += __shfl_xor_sync(0xffffffffu, p0, off);
            p1 += __shfl_xor_sync(0xffffffffu, p1, off);
        }
        float nm0 = fmaxf(m0, p0), nm1 = fmaxf(m1, p1);
        float s0 = __expf(m0 - nm0), s1 = __expf(m1 - nm1);
        float w0 = __expf(p0 - nm0), w1 = __expf(p1 - nm1);
        d0 = d0 * s0 + w0;          d1 = d1 * s1 + w1;
        c0 = c0 * s0 + w0 * v0;     c1 = c1 * s0 + w0 * v1;
        c2 = c2 * s1 + w1 * v2;     c3 = c3 * s1 + w1 * v3;
        m0 = nm0; m1 = nm1;
    }
    float i0 = 1.f / (d0 + 1e-16f), i1 = 1.f / (d1 + 1e-16f);
    float o0 = c0 * i0 + bias1[lane];
    float o1 = c1 * i0 + bias1[lane + 32];
    float o2 = c2 * i1 + bias1[lane + 64];
    float o3 = c3 * i1 + bias1[lane + 96];

    float sum = o0 + o1 + o2 + o3;
    float sq  = o0 * o0 + o1 * o1 + o2 * o2 + o3 * o3;
#pragma unroll
    for (int off = 16; off; off >>= 1) {
        sum += __shfl_xor_sync(0xffffffffu, sum, off);
        sq  += __shfl_xor_sync(0xffffffffu, sq,  off);
    }
    float mu = sum * (1.f / 128.f);
    float var = sq * (1.f / 128.f) - mu * mu;
    float rs = rsqrtf(var + 1e-5f);

    float* ho = g_h1 + (size_t)node * 128;
    float t;
    t = (o0 - mu) * rs * g1[lane]      + be1[lane];      ho[lane]      = (t > 0.f) ? t : expm1f(t);
    t = (o1 - mu) * rs * g1[lane + 32] + be1[lane + 32]; ho[lane + 32] = (t > 0.f) ? t : expm1f(t);
    t = (o2 - mu) * rs * g1[lane + 64] + be1[lane + 64]; ho[lane + 64] = (t > 0.f) ? t : expm1f(t);
    t = (o3 - mu) * rs * g1[lane + 96] + be1[lane + 96]; ho[lane + 96] = (t > 0.f) ? t : expm1f(t);
}

// ---------------- layer 2: warp-per-dst online segment softmax ----------------
__global__ __launch_bounds__(256) void k_agg2(
    const float* __restrict__ att2, const float* __restrict__ bias2,
    float* __restrict__ out)
{
    int node = (blockIdx.x * blockDim.x + threadIdx.x) >> 5;
    if (node >= NNODES) return;
    int lane = threadIdx.x & 31;

    float xr0 = g_xlr2[(size_t)node * 128 + 64 + lane];
    float xr1 = g_xlr2[(size_t)node * 128 + 96 + lane];
    float a0 = att2[lane], a1 = att2[lane + 32];

    float m = -1e30f, d = 0.f, c0 = 0.f, c1 = 0.f;
    int beg = g_rowptr[node], end = g_rowptr[node + 1];
    for (int i = beg; i < end; i++) {
        int s = g_srcs[i];
        float v0 = g_xlr2[(size_t)s * 128 + lane];
        float v1 = g_xlr2[(size_t)s * 128 + 32 + lane];
        float e0 = v0 + xr0; e0 = (e0 > 0.f) ? e0 : NEGS * e0;
        float e1 = v1 + xr1; e1 = (e1 > 0.f) ? e1 : NEGS * e1;
        float p = a0 * e0 + a1 * e1;
#pragma unroll
        for (int off = 16; off; off >>= 1) p += __shfl_xor_sync(0xffffffffu, p, off);
        float nm = fmaxf(m, p);
        float sc = __expf(m - nm);
        float w  = __expf(p - nm);
        d  = d  * sc + w;
        c0 = c0 * sc + w * v0;
        c1 = c1 * sc + w * v1;
        m = nm;
    }
    float inv = 1.f / (d + 1e-16f);
    out[(size_t)node * 64 + lane]      = c0 * inv + bias2[lane];
    out[(size_t)node * 64 + lane + 32] = c1 * inv + bias2[lane + 32];
}

// ---------------- global mean pool ----------------
__global__ __launch_bounds__(256) void k_pool(const int* __restrict__ batch,
                                              const float* __restrict__ emb)
{
    int node = (blockIdx.x * blockDim.x + threadIdx.x) >> 5;
    if (node >= NNODES) return;
    int lane = threadIdx.x & 31;
    int g = batch[node];
    atomicAdd(&g_gsum[g * 64 + lane],      emb[(size_t)node * 64 + lane]);
    atomicAdd(&g_gsum[g * 64 + lane + 32], emb[(size_t)node * 64 + lane + 32]);
    if (lane == 0) atomicAdd(&g_gcnt[g], 1);
}

__global__ void k_final(float* __restrict__ out) {
    int i = blockIdx.x * blockDim.x + threadIdx.x;
    if (i < NGRAPH * 64) {
        int g = i >> 6;
        float cnt = (float)g_gcnt[g];
        out[(size_t)NNODES * 64 + i] = g_gsum[i] / fmaxf(cnt, 1.f);
    }
}

// ---------------- launch ----------------
extern "C" void kernel_launch(void* const* d_in, const int* in_sizes, int n_in,
                              void* d_out, int out_size)
{
    const float* x     = (const float*)d_in[0];
    const int*   ei    = (const int*)  d_in[1];
    const int*   batch = (const int*)  d_in[2];
    const float* W1l   = (const float*)d_in[3];
    const float* b1l   = (const float*)d_in[4];
    const float* W1r   = (const float*)d_in[5];
    const float* b1r   = (const float*)d_in[6];
    const float* att1  = (const float*)d_in[7];
    const float* bias1 = (const float*)d_in[8];
    const float* g1    = (const float*)d_in[9];
    const float* be1   = (const float*)d_in[10];
    const float* W2l   = (const float*)d_in[11];
    const float* b2l   = (const float*)d_in[12];
    const float* W2r   = (const float*)d_in[13];
    const float* b2r   = (const float*)d_in[14];
    const float* att2  = (const float*)d_in[15];
    const float* bias2 = (const float*)d_in[16];
    float* out = (float*)d_out;

    float *xlr1p, *h1p, *xlr2p, *bias1p, *bias2p;
    __nv_bfloat16 *b1ep, *b2ep;
    cudaGetSymbolAddress((void**)&xlr1p, g_xlr1);
    cudaGetSymbolAddress((void**)&h1p,   g_h1);
    cudaGetSymbolAddress((void**)&xlr2p, g_xlr2);
    cudaGetSymbolAddress((void**)&b1ep,  g_B1e);
    cudaGetSymbolAddress((void**)&b2ep,  g_B2e);
    cudaGetSymbolAddress((void**)&bias1p, g_bias1);
    cudaGetSymbolAddress((void**)&bias2p, g_bias2);

    cudaFuncSetAttribute(k_hmma, cudaFuncAttributeMaxDynamicSharedMemorySize, SM_TOT);

    int rowTiles = (NNODES + 127) / 128;
    int aggBlocks = (NNODES + 7) / 8;
    int nb = (NNODES + 1023) / 1024;

    // Launch order puts the layer-1 GEMM 6th so ncu (-s 5 -c 1) profiles it.
    k_prep<<<(256 * 256 + 255) / 256, 256>>>(W1l, W1r, b1l, b1r, W2l, W2r, b2l, b2r); // 1
    k_zero<<<(NNODES + 255) / 256, 256>>>();                                          // 2
    k_hist<<<(NEDGES + 255) / 256, 256>>>(ei);                                        // 3
    k_scan1<<<nb, 1024>>>();                                                          // 4
    k_scan2<<<1, 128>>>(nb);                                                          // 5
    k_hmma<<<dim3(rowTiles, 2), 256, SM_TOT>>>(x, b1ep, bias1p, xlr1p, NNODES, 256);  // 6 <- profiled
    k_scan3<<<nb, 1024>>>();                                                          // 7
    k_scatter<<<(NEDGES + 255) / 256, 256>>>(ei);                                     // 8
    k_agg1<<<aggBlocks, 256>>>(att1, bias1, g1, be1);                                 // 9
    k_hmma<<<dim3(rowTiles, 1), 256, SM_TOT>>>(h1p, b2ep, bias2p, xlr2p, NNODES, 128);// 10
    k_agg2<<<aggBlocks, 256>>>(att2, bias2, out);                                     // 11
    if (out_size >= NNODES * 64 + NGRAPH * 64) {
        k_pool<<<aggBlocks, 256>>>(batch, out);                                       // 12
        k_final<<<(NGRAPH * 64 + 255) / 256, 256>>>(out);                             // 13
    }
}